// round 14
// baseline (speedup 1.0000x reference)
#include <cuda_runtime.h>
#include <cuda_fp16.h>
#include <cstdint>

#define N_NODES 65536
#define N_EDGES 1048576
#define FEAT    64
#define LDH     72            // halves per smem row (64 + 8 pad)

// ------------------------- device scratch (no allocs) -----------------------
__device__ __align__(16) __half g_support_h[(size_t)N_NODES * FEAT]; // 8 MB
__device__ __align__(16) int   g_cnt[N_NODES];   // zero-init; self-cleaned per run
__device__ __align__(16) int   g_rs[N_NODES + 4];
__device__ __align__(16) int   g_cur[N_NODES];
__device__ __align__(16) int   g_bsum[64];
__device__ __align__(16) int2  g_epair[N_EDGES];
__device__ unsigned g_barcnt;
__device__ unsigned g_bargen;

// ---- mma helpers ------------------------------------------------------------
__device__ __forceinline__ uint32_t smem_u32(const void* p) {
    return (uint32_t)__cvta_generic_to_shared(p);
}
__device__ __forceinline__ void ldsm_x4(uint32_t& r0, uint32_t& r1,
                                        uint32_t& r2, uint32_t& r3, uint32_t a) {
    asm volatile("ldmatrix.sync.aligned.m8n8.x4.shared.b16 {%0,%1,%2,%3}, [%4];"
                 : "=r"(r0), "=r"(r1), "=r"(r2), "=r"(r3) : "r"(a));
}
__device__ __forceinline__ void ldsm_x2t(uint32_t& r0, uint32_t& r1, uint32_t a) {
    asm volatile("ldmatrix.sync.aligned.m8n8.x2.trans.shared.b16 {%0,%1}, [%2];"
                 : "=r"(r0), "=r"(r1) : "r"(a));
}
__device__ __forceinline__ void mma16816(float* c, uint32_t a0, uint32_t a1,
                                         uint32_t a2, uint32_t a3,
                                         uint32_t b0, uint32_t b1) {
    asm volatile(
        "mma.sync.aligned.m16n8k16.row.col.f32.f16.f16.f32 "
        "{%0,%1,%2,%3}, {%4,%5,%6,%7}, {%8,%9}, {%0,%1,%2,%3};"
        : "+f"(c[0]), "+f"(c[1]), "+f"(c[2]), "+f"(c[3])
        : "r"(a0), "r"(a1), "r"(a2), "r"(a3), "r"(b0), "r"(b1));
}

// ---------------------------------------------------------------------------
// Kernel 1: tensor-core GEMM (128 rows/block) + edge-row histogram (2048 edges).
// X,W converted to fp16 in smem; HMMA m16n8k16 with fp32 accum; fp16 out.
// ---------------------------------------------------------------------------
__global__ __launch_bounds__(256) void gemm_hist(const float* __restrict__ X,
                                                 const float* __restrict__ W,
                                                 const int4*  __restrict__ erow4) {
    __shared__ __half Xh[128 * LDH];
    __shared__ __half Wh[64 * LDH];

    const int tid  = threadIdx.x;
    const int lane = tid & 31;
    const int warp = tid >> 5;
    const int base = blockIdx.x * 128;

    // ---- load + convert X tile (128x64 f32 -> fp16 smem) ----
    const float4* X4 = (const float4*)X;
#pragma unroll
    for (int i = 0; i < 8; i++) {
        const int idx = tid + i * 256;       // 0..2047
        const int row = idx >> 4;
        const int q   = idx & 15;
        const float4 x = X4[(size_t)(base + row) * 16 + q];
        const __half2 h0 = __floats2half2_rn(x.x, x.y);
        const __half2 h1 = __floats2half2_rn(x.z, x.w);
        uint2 st;
        st.x = *(const unsigned*)&h0;
        st.y = *(const unsigned*)&h1;
        *(uint2*)&Xh[row * LDH + q * 4] = st;
    }
    // ---- load + convert W (64x64) ----
    const float4* W4 = (const float4*)W;
#pragma unroll
    for (int i = 0; i < 4; i++) {
        const int idx = tid + i * 256;       // 0..1023
        const int row = idx >> 4;
        const int q   = idx & 15;
        const float4 w = W4[row * 16 + q];
        const __half2 h0 = __floats2half2_rn(w.x, w.y);
        const __half2 h1 = __floats2half2_rn(w.z, w.w);
        uint2 st;
        st.x = *(const unsigned*)&h0;
        st.y = *(const unsigned*)&h1;
        *(uint2*)&Wh[row * LDH + q * 4] = st;
    }

    // ---- histogram chunk (atomics drain under the MMA work) ----
#pragma unroll
    for (int p = 0; p < 2; p++) {
        const int4 r = erow4[blockIdx.x * 512 + p * 256 + tid];
        atomicAdd(&g_cnt[r.x], 1);
        atomicAdd(&g_cnt[r.y], 1);
        atomicAdd(&g_cnt[r.z], 1);
        atomicAdd(&g_cnt[r.w], 1);
    }

    __syncthreads();

    // ---- MMA: each warp does rows [16*warp, 16*warp+16), all 64 cols ----
    const int rowbase = warp * 16;
    float c[8][4];
#pragma unroll
    for (int nt = 0; nt < 8; nt++)
#pragma unroll
        for (int j = 0; j < 4; j++) c[nt][j] = 0.f;

    const int arow = rowbase + (lane & 15);
    const int acolb = (lane >> 4) * 8;
    const int brow15 = lane & 15;

#pragma unroll
    for (int kt = 0; kt < 4; kt++) {
        uint32_t a0, a1, a2, a3;
        ldsm_x4(a0, a1, a2, a3, smem_u32(&Xh[arow * LDH + kt * 16 + acolb]));
#pragma unroll
        for (int nt = 0; nt < 8; nt++) {
            uint32_t b0, b1;
            ldsm_x2t(b0, b1, smem_u32(&Wh[(kt * 16 + brow15) * LDH + nt * 8]));
            mma16816(c[nt], a0, a1, a2, a3, b0, b1);
        }
    }

    // ---- pack fp32 C frags -> fp16 support ----
    // thread holds (row g, cols 2t..2t+1) and (row g+8, cols 2t..2t+1) per ntile
    const int g   = lane >> 2;
    const int tg  = lane & 3;
    const size_t r0 = (size_t)(base + rowbase + g) * FEAT;
    const size_t r1 = r0 + 8 * FEAT;
#pragma unroll
    for (int nt = 0; nt < 8; nt++) {
        const int col = nt * 8 + tg * 2;
        const __half2 lo = __floats2half2_rn(c[nt][0], c[nt][1]);
        const __half2 hi = __floats2half2_rn(c[nt][2], c[nt][3]);
        *(__half2*)&g_support_h[r0 + col] = lo;
        *(__half2*)&g_support_h[r1 + col] = hi;
    }
}

// ---------------------------------------------------------------------------
// Kernel 2: full CSR scan (64 blocks, internal grid barrier). Self-cleans cnt.
// ---------------------------------------------------------------------------
__device__ __forceinline__ void gbar64() {
    __syncthreads();
    if (threadIdx.x == 0) {
        __threadfence();
        const unsigned gen = *(volatile unsigned*)&g_bargen;
        if (atomicAdd(&g_barcnt, 1u) == 63u) {
            g_barcnt = 0;
            __threadfence();
            *(volatile unsigned*)&g_bargen = gen + 1u;
        } else {
            while (*(volatile unsigned*)&g_bargen == gen) { __nanosleep(32); }
        }
    }
    __syncthreads();
}

__global__ __launch_bounds__(256) void scan_fused() {
    __shared__ int wsum[8];
    const int tid = threadIdx.x;
    const int bid = blockIdx.x;
    const int i = bid * 256 + tid;

    const int4 c = ((const int4*)g_cnt)[i];
    const int s = c.x + c.y + c.z + c.w;

    const int lane = tid & 31, wid = tid >> 5;
    int x = s;
#pragma unroll
    for (int d = 1; d < 32; d <<= 1) {
        const int y = __shfl_up_sync(0xFFFFFFFFu, x, d);
        if (lane >= d) x += y;
    }
    if (lane == 31) wsum[wid] = x;
    __syncthreads();
    if (wid == 0) {
        int w = (lane < 8) ? wsum[lane] : 0;
#pragma unroll
        for (int d = 1; d < 8; d <<= 1) {
            const int y = __shfl_up_sync(0xFFFFFFFFu, w, d);
            if (lane >= d) w += y;
        }
        if (lane < 8) wsum[lane] = w;
    }
    __syncthreads();
    const int incl = x + (wid > 0 ? wsum[wid - 1] : 0);
    const int ex = incl - s;
    if (tid == 255) g_bsum[bid] = incl;
    gbar64();

    if (bid == 0 && tid < 32) {
        const int a = __ldcg(&g_bsum[tid]);
        const int b = __ldcg(&g_bsum[tid + 32]);
        int ia = a, ib = b;
#pragma unroll
        for (int d = 1; d < 32; d <<= 1) {
            const int ya = __shfl_up_sync(0xFFFFFFFFu, ia, d);
            const int yb = __shfl_up_sync(0xFFFFFFFFu, ib, d);
            if (tid >= d) { ia += ya; ib += yb; }
        }
        const int lowtot = __shfl_sync(0xFFFFFFFFu, ia, 31);
        g_bsum[tid]      = ia - a;
        g_bsum[tid + 32] = lowtot + ib - b;
    }
    gbar64();

    const int off = __ldcg(&g_bsum[bid]) + ex;
    const int4 rs = make_int4(off, off + c.x, off + c.x + c.y, off + c.x + c.y + c.z);
    ((int4*)g_rs)[i]  = rs;
    ((int4*)g_cur)[i] = rs;
    ((int4*)g_cnt)[i] = make_int4(0, 0, 0, 0);
    if (i == 0) g_rs[N_NODES] = N_EDGES;
}

// ---------------------------------------------------------------------------
// Kernel 3: reorder edges into CSR (col, val) pairs
// ---------------------------------------------------------------------------
__global__ __launch_bounds__(256) void reorder(const int4*   __restrict__ erow4,
                                               const int4*   __restrict__ ecol4,
                                               const float4* __restrict__ eval4) {
    const unsigned i = blockIdx.x * 256u + threadIdx.x;
    const int4   r = erow4[i];
    const int4   c = ecol4[i];
    const float4 v = eval4[i];
    int p;
    p = atomicAdd(&g_cur[r.x], 1); g_epair[p] = make_int2(c.x, __float_as_int(v.x));
    p = atomicAdd(&g_cur[r.y], 1); g_epair[p] = make_int2(c.y, __float_as_int(v.y));
    p = atomicAdd(&g_cur[r.z], 1); g_epair[p] = make_int2(c.z, __float_as_int(v.z));
    p = atomicAdd(&g_cur[r.w], 1); g_epair[p] = make_int2(c.w, __float_as_int(v.w));
}

// ---------------------------------------------------------------------------
// Kernel 4: SpMM + bias + ReLU, 8 threads/row, software-pipelined unroll-4.
// ---------------------------------------------------------------------------
__global__ __launch_bounds__(256) void spmm_fused(float* __restrict__ out,
                                                  const float* __restrict__ bias) {
    const int r  = blockIdx.x * 32 + (threadIdx.x >> 3);
    const int qi = threadIdx.x & 7;

    const int s = g_rs[r];
    const int e = g_rs[r + 1];
    const __half* supp = g_support_h;

    float acc[8];
#pragma unroll
    for (int j = 0; j < 8; j++) acc[j] = 0.f;

    int i = s;
    for (; i + 4 <= e; i += 4) {
        const int2 p0 = g_epair[i + 0];
        const int2 p1 = g_epair[i + 1];
        const int2 p2 = g_epair[i + 2];
        const int2 p3 = g_epair[i + 3];
        const uint4 h0 = *(const uint4*)(supp + ((size_t)p0.x << 6) + (qi << 3));
        const uint4 h1 = *(const uint4*)(supp + ((size_t)p1.x << 6) + (qi << 3));
        const uint4 h2 = *(const uint4*)(supp + ((size_t)p2.x << 6) + (qi << 3));
        const uint4 h3 = *(const uint4*)(supp + ((size_t)p3.x << 6) + (qi << 3));
        const float v0 = __int_as_float(p0.y);
        const float v1 = __int_as_float(p1.y);
        const float v2 = __int_as_float(p2.y);
        const float v3 = __int_as_float(p3.y);
        float2 f;
        f = __half22float2(*(const __half2*)&h0.x); acc[0] += v0 * f.x; acc[1] += v0 * f.y;
        f = __half22float2(*(const __half2*)&h0.y); acc[2] += v0 * f.x; acc[3] += v0 * f.y;
        f = __half22float2(*(const __half2*)&h0.z); acc[4] += v0 * f.x; acc[5] += v0 * f.y;
        f = __half22float2(*(const __half2*)&h0.w); acc[6] += v0 * f.x; acc[7] += v0 * f.y;
        f = __half22float2(*(const __half2*)&h1.x); acc[0] += v1 * f.x; acc[1] += v1 * f.y;
        f = __half22float2(*(const __half2*)&h1.y); acc[2] += v1 * f.x; acc[3] += v1 * f.y;
        f = __half22float2(*(const __half2*)&h1.z); acc[4] += v1 * f.x; acc[5] += v1 * f.y;
        f = __half22float2(*(const __half2*)&h1.w); acc[6] += v1 * f.x; acc[7] += v1 * f.y;
        f = __half22float2(*(const __half2*)&h2.x); acc[0] += v2 * f.x; acc[1] += v2 * f.y;
        f = __half22float2(*(const __half2*)&h2.y); acc[2] += v2 * f.x; acc[3] += v2 * f.y;
        f = __half22float2(*(const __half2*)&h2.z); acc[4] += v2 * f.x; acc[5] += v2 * f.y;
        f = __half22float2(*(const __half2*)&h2.w); acc[6] += v2 * f.x; acc[7] += v2 * f.y;
        f = __half22float2(*(const __half2*)&h3.x); acc[0] += v3 * f.x; acc[1] += v3 * f.y;
        f = __half22float2(*(const __half2*)&h3.y); acc[2] += v3 * f.x; acc[3] += v3 * f.y;
        f = __half22float2(*(const __half2*)&h3.z); acc[4] += v3 * f.x; acc[5] += v3 * f.y;
        f = __half22float2(*(const __half2*)&h3.w); acc[6] += v3 * f.x; acc[7] += v3 * f.y;
    }
    for (; i < e; i++) {
        const int2 p0 = g_epair[i];
        const float v0 = __int_as_float(p0.y);
        const uint4 h0 = *(const uint4*)(supp + ((size_t)p0.x << 6) + (qi << 3));
        float2 f;
        f = __half22float2(*(const __half2*)&h0.x); acc[0] += v0 * f.x; acc[1] += v0 * f.y;
        f = __half22float2(*(const __half2*)&h0.y); acc[2] += v0 * f.x; acc[3] += v0 * f.y;
        f = __half22float2(*(const __half2*)&h0.z); acc[4] += v0 * f.x; acc[5] += v0 * f.y;
        f = __half22float2(*(const __half2*)&h0.w); acc[6] += v0 * f.x; acc[7] += v0 * f.y;
    }

    const float4 b0 = *(const float4*)(bias + qi * 8);
    const float4 b1 = *(const float4*)(bias + qi * 8 + 4);
    float4 o0, o1;
    o0.x = fmaxf(acc[0] + b0.x, 0.f); o0.y = fmaxf(acc[1] + b0.y, 0.f);
    o0.z = fmaxf(acc[2] + b0.z, 0.f); o0.w = fmaxf(acc[3] + b0.w, 0.f);
    o1.x = fmaxf(acc[4] + b1.x, 0.f); o1.y = fmaxf(acc[5] + b1.y, 0.f);
    o1.z = fmaxf(acc[6] + b1.z, 0.f); o1.w = fmaxf(acc[7] + b1.w, 0.f);
    float* po = out + (size_t)r * FEAT + qi * 8;
    *(float4*)po       = o0;
    *(float4*)(po + 4) = o1;
}

// ---------------------------------------------------------------------------
extern "C" void kernel_launch(void* const* d_in, const int* in_sizes, int n_in,
                              void* d_out, int out_size) {
    const float* X    = (const float*)d_in[0];
    const int*   erow = (const int*)  d_in[1];
    const int*   ecol = (const int*)  d_in[2];
    const float* eval = (const float*)d_in[3];
    const float* W    = (const float*)d_in[4];
    const float* bias = (const float*)d_in[5];
    float* out = (float*)d_out;

    gemm_hist<<<N_NODES / 128, 256>>>(X, W, (const int4*)erow);
    scan_fused<<<64, 256>>>();
    reorder<<<N_EDGES / 1024, 256>>>((const int4*)erow, (const int4*)ecol,
                                     (const float4*)eval);
    spmm_fused<<<N_NODES / 32, 256>>>(out, bias);
}

// round 17
// speedup vs baseline: 1.2474x; 1.2474x over previous
#include <cuda_runtime.h>
#include <cuda_fp16.h>
#include <cstdint>

#define N_NODES 65536
#define N_EDGES 1048576
#define FEAT    64

// ------------------------- device scratch (no allocs) -----------------------
__device__ __align__(16) __half g_support_h[(size_t)N_NODES * FEAT]; // 8 MB
__device__ __align__(16) int   g_cnt[N_NODES];   // zero-init; self-cleaned per run
__device__ __align__(16) int   g_rs[N_NODES + 4];
__device__ __align__(16) int   g_cur[N_NODES];
__device__ __align__(16) int   g_bsum[64];
__device__ __align__(16) int2  g_epair[N_EDGES];
__device__ unsigned g_barcnt;
__device__ unsigned g_bargen;

// ---- packed f32x2 helpers ---------------------------------------------------
__device__ __forceinline__ unsigned long long pk2(float x, float y) {
    unsigned long long r;
    asm("mov.b64 %0, {%1, %2};" : "=l"(r) : "f"(x), "f"(y));
    return r;
}
__device__ __forceinline__ void fma2(unsigned long long& d,
                                     unsigned long long a, unsigned long long b) {
    asm("fma.rn.f32x2 %0, %1, %2, %0;" : "+l"(d) : "l"(a), "l"(b));
}
__device__ __forceinline__ float2 up2(unsigned long long v) {
    float2 f;
    asm("mov.b64 {%0, %1}, %2;" : "=f"(f.x), "=f"(f.y) : "l"(v));
    return f;
}

// ---------------------------------------------------------------------------
// Kernel 1: GEMM tile (64 rows) + edge-row histogram chunk (1024 edges).
// (R13-proven version, f32x2 FMA, fp16 output)
// ---------------------------------------------------------------------------
__global__ __launch_bounds__(256) void gemm_hist(const float* __restrict__ X,
                                                 const float* __restrict__ W,
                                                 const int4*  __restrict__ erow4) {
    __shared__ float4 Ws[64][16];
    __shared__ float4 Xs[64][16];

    const int tid  = threadIdx.x;
    const int base = blockIdx.x * 64;

    const float4* X4 = (const float4*)(X + (size_t)base * FEAT);
    const float4* W4 = (const float4*)W;
    float4* XsF = (float4*)Xs;
    float4* WsF = (float4*)Ws;
#pragma unroll
    for (int i = 0; i < 4; i++) {
        const int idx = tid + i * 256;
        XsF[idx] = X4[idx];
        WsF[idx] = W4[idx];
    }

    const int4 r = erow4[blockIdx.x * 256 + tid];
    atomicAdd(&g_cnt[r.x], 1);
    atomicAdd(&g_cnt[r.y], 1);
    atomicAdd(&g_cnt[r.z], 1);
    atomicAdd(&g_cnt[r.w], 1);

    __syncthreads();

    const int rt = tid >> 4;
    const int ct = tid & 15;

    unsigned long long acc[4][2];
#pragma unroll
    for (int i = 0; i < 4; i++) { acc[i][0] = pk2(0.f, 0.f); acc[i][1] = pk2(0.f, 0.f); }

#pragma unroll
    for (int kk = 0; kk < 16; kk++) {
        const float4 w0 = Ws[kk * 4 + 0][ct];
        const float4 w1 = Ws[kk * 4 + 1][ct];
        const float4 w2 = Ws[kk * 4 + 2][ct];
        const float4 w3 = Ws[kk * 4 + 3][ct];
        const unsigned long long wp00 = pk2(w0.x, w0.y), wp01 = pk2(w0.z, w0.w);
        const unsigned long long wp10 = pk2(w1.x, w1.y), wp11 = pk2(w1.z, w1.w);
        const unsigned long long wp20 = pk2(w2.x, w2.y), wp21 = pk2(w2.z, w2.w);
        const unsigned long long wp30 = pk2(w3.x, w3.y), wp31 = pk2(w3.z, w3.w);
#pragma unroll
        for (int i = 0; i < 4; i++) {
            const float4 x = Xs[rt + 16 * i][kk];
            unsigned long long xx;
            xx = pk2(x.x, x.x); fma2(acc[i][0], xx, wp00); fma2(acc[i][1], xx, wp01);
            xx = pk2(x.y, x.y); fma2(acc[i][0], xx, wp10); fma2(acc[i][1], xx, wp11);
            xx = pk2(x.z, x.z); fma2(acc[i][0], xx, wp20); fma2(acc[i][1], xx, wp21);
            xx = pk2(x.w, x.w); fma2(acc[i][0], xx, wp30); fma2(acc[i][1], xx, wp31);
        }
    }

#pragma unroll
    for (int i = 0; i < 4; i++) {
        const int row = base + rt + 16 * i;
        const float2 a = up2(acc[i][0]);
        const float2 b = up2(acc[i][1]);
        const __half2 ha = __floats2half2_rn(a.x, a.y);
        const __half2 hb = __floats2half2_rn(b.x, b.y);
        uint2 st;
        st.x = *(const unsigned*)&ha;
        st.y = *(const unsigned*)&hb;
        *(uint2*)(g_support_h + (size_t)row * FEAT + ct * 4) = st;
    }
}

// ---------------------------------------------------------------------------
// Kernel 2: full CSR scan (64 blocks, internal grid barrier). Self-cleans cnt.
// ---------------------------------------------------------------------------
__device__ __forceinline__ void gbar64() {
    __syncthreads();
    if (threadIdx.x == 0) {
        __threadfence();
        const unsigned gen = *(volatile unsigned*)&g_bargen;
        if (atomicAdd(&g_barcnt, 1u) == 63u) {
            g_barcnt = 0;
            __threadfence();
            *(volatile unsigned*)&g_bargen = gen + 1u;
        } else {
            while (*(volatile unsigned*)&g_bargen == gen) { __nanosleep(32); }
        }
    }
    __syncthreads();
}

__global__ __launch_bounds__(256) void scan_fused() {
    __shared__ int wsum[8];
    const int tid = threadIdx.x;
    const int bid = blockIdx.x;
    const int i = bid * 256 + tid;

    const int4 c = ((const int4*)g_cnt)[i];
    const int s = c.x + c.y + c.z + c.w;

    const int lane = tid & 31, wid = tid >> 5;
    int x = s;
#pragma unroll
    for (int d = 1; d < 32; d <<= 1) {
        const int y = __shfl_up_sync(0xFFFFFFFFu, x, d);
        if (lane >= d) x += y;
    }
    if (lane == 31) wsum[wid] = x;
    __syncthreads();
    if (wid == 0) {
        int w = (lane < 8) ? wsum[lane] : 0;
#pragma unroll
        for (int d = 1; d < 8; d <<= 1) {
            const int y = __shfl_up_sync(0xFFFFFFFFu, w, d);
            if (lane >= d) w += y;
        }
        if (lane < 8) wsum[lane] = w;
    }
    __syncthreads();
    const int incl = x + (wid > 0 ? wsum[wid - 1] : 0);
    const int ex = incl - s;
    if (tid == 255) g_bsum[bid] = incl;
    gbar64();

    if (bid == 0 && tid < 32) {
        const int a = __ldcg(&g_bsum[tid]);
        const int b = __ldcg(&g_bsum[tid + 32]);
        int ia = a, ib = b;
#pragma unroll
        for (int d = 1; d < 32; d <<= 1) {
            const int ya = __shfl_up_sync(0xFFFFFFFFu, ia, d);
            const int yb = __shfl_up_sync(0xFFFFFFFFu, ib, d);
            if (tid >= d) { ia += ya; ib += yb; }
        }
        const int lowtot = __shfl_sync(0xFFFFFFFFu, ia, 31);
        g_bsum[tid]      = ia - a;
        g_bsum[tid + 32] = lowtot + ib - b;
    }
    gbar64();

    const int off = __ldcg(&g_bsum[bid]) + ex;
    const int4 rs = make_int4(off, off + c.x, off + c.x + c.y, off + c.x + c.y + c.z);
    ((int4*)g_rs)[i]  = rs;
    ((int4*)g_cur)[i] = rs;
    ((int4*)g_cnt)[i] = make_int4(0, 0, 0, 0);
    if (i == 0) g_rs[N_NODES] = N_EDGES;
}

// ---------------------------------------------------------------------------
// Kernel 3: reorder edges into CSR pairs, 8 edges/thread (MLP=8 on atomics).
// Two coalesced int4 streams at i and i + half.
// ---------------------------------------------------------------------------
__global__ __launch_bounds__(256) void reorder(const int4*   __restrict__ erow4,
                                               const int4*   __restrict__ ecol4,
                                               const float4* __restrict__ eval4) {
    const unsigned i0 = blockIdx.x * 256u + threadIdx.x;          // 0..131071
    const unsigned i1 = i0 + (N_EDGES / 4 / 2);                   // second half

    const int4   ra = erow4[i0];
    const int4   rb = erow4[i1];
    const int4   ca = ecol4[i0];
    const int4   cb = ecol4[i1];
    const float4 va = eval4[i0];
    const float4 vb = eval4[i1];

    // 8 independent atomic round-trips in flight
    const int pa0 = atomicAdd(&g_cur[ra.x], 1);
    const int pa1 = atomicAdd(&g_cur[ra.y], 1);
    const int pa2 = atomicAdd(&g_cur[ra.z], 1);
    const int pa3 = atomicAdd(&g_cur[ra.w], 1);
    const int pb0 = atomicAdd(&g_cur[rb.x], 1);
    const int pb1 = atomicAdd(&g_cur[rb.y], 1);
    const int pb2 = atomicAdd(&g_cur[rb.z], 1);
    const int pb3 = atomicAdd(&g_cur[rb.w], 1);

    g_epair[pa0] = make_int2(ca.x, __float_as_int(va.x));
    g_epair[pa1] = make_int2(ca.y, __float_as_int(va.y));
    g_epair[pa2] = make_int2(ca.z, __float_as_int(va.z));
    g_epair[pa3] = make_int2(ca.w, __float_as_int(va.w));
    g_epair[pb0] = make_int2(cb.x, __float_as_int(vb.x));
    g_epair[pb1] = make_int2(cb.y, __float_as_int(vb.y));
    g_epair[pb2] = make_int2(cb.z, __float_as_int(vb.z));
    g_epair[pb3] = make_int2(cb.w, __float_as_int(vb.w));
}

// ---------------------------------------------------------------------------
// Kernel 4: SpMM + bias + ReLU, 8 threads/row, unroll-4 WITH cross-iteration
// epair prefetch (gather addresses ready at iteration top).
// ---------------------------------------------------------------------------
__global__ __launch_bounds__(256) void spmm_fused(float* __restrict__ out,
                                                  const float* __restrict__ bias) {
    const int r  = blockIdx.x * 32 + (threadIdx.x >> 3);
    const int qi = threadIdx.x & 7;

    const int s = g_rs[r];
    const int e = g_rs[r + 1];
    const __half* supp = g_support_h;

    float acc[8];
#pragma unroll
    for (int j = 0; j < 8; j++) acc[j] = 0.f;

    int i = s;
    int2 q0, q1, q2, q3;
    const bool have = (i + 4 <= e);
    if (have) {
        q0 = g_epair[i + 0]; q1 = g_epair[i + 1];
        q2 = g_epair[i + 2]; q3 = g_epair[i + 3];
    }
    for (; i + 8 <= e; i += 4) {
        // prefetch next quad (independent of current gathers)
        const int2 n0 = g_epair[i + 4];
        const int2 n1 = g_epair[i + 5];
        const int2 n2 = g_epair[i + 6];
        const int2 n3 = g_epair[i + 7];

        const uint4 h0 = *(const uint4*)(supp + ((size_t)q0.x << 6) + (qi << 3));
        const uint4 h1 = *(const uint4*)(supp + ((size_t)q1.x << 6) + (qi << 3));
        const uint4 h2 = *(const uint4*)(supp + ((size_t)q2.x << 6) + (qi << 3));
        const uint4 h3 = *(const uint4*)(supp + ((size_t)q3.x << 6) + (qi << 3));
        const float v0 = __int_as_float(q0.y);
        const float v1 = __int_as_float(q1.y);
        const float v2 = __int_as_float(q2.y);
        const float v3 = __int_as_float(q3.y);
        float2 f;
        f = __half22float2(*(const __half2*)&h0.x); acc[0] += v0 * f.x; acc[1] += v0 * f.y;
        f = __half22float2(*(const __half2*)&h0.y); acc[2] += v0 * f.x; acc[3] += v0 * f.y;
        f = __half22float2(*(const __half2*)&h0.z); acc[4] += v0 * f.x; acc[5] += v0 * f.y;
        f = __half22float2(*(const __half2*)&h0.w); acc[6] += v0 * f.x; acc[7] += v0 * f.y;
        f = __half22float2(*(const __half2*)&h1.x); acc[0] += v1 * f.x; acc[1] += v1 * f.y;
        f = __half22float2(*(const __half2*)&h1.y); acc[2] += v1 * f.x; acc[3] += v1 * f.y;
        f = __half22float2(*(const __half2*)&h1.z); acc[4] += v1 * f.x; acc[5] += v1 * f.y;
        f = __half22float2(*(const __half2*)&h1.w); acc[6] += v1 * f.x; acc[7] += v1 * f.y;
        f = __half22float2(*(const __half2*)&h2.x); acc[0] += v2 * f.x; acc[1] += v2 * f.y;
        f = __half22float2(*(const __half2*)&h2.y); acc[2] += v2 * f.x; acc[3] += v2 * f.y;
        f = __half22float2(*(const __half2*)&h2.z); acc[4] += v2 * f.x; acc[5] += v2 * f.y;
        f = __half22float2(*(const __half2*)&h2.w); acc[6] += v2 * f.x; acc[7] += v2 * f.y;
        f = __half22float2(*(const __half2*)&h3.x); acc[0] += v3 * f.x; acc[1] += v3 * f.y;
        f = __half22float2(*(const __half2*)&h3.y); acc[2] += v3 * f.x; acc[3] += v3 * f.y;
        f = __half22float2(*(const __half2*)&h3.z); acc[4] += v3 * f.x; acc[5] += v3 * f.y;
        f = __half22float2(*(const __half2*)&h3.w); acc[6] += v3 * f.x; acc[7] += v3 * f.y;

        q0 = n0; q1 = n1; q2 = n2; q3 = n3;
    }
    if (have) {
        // drain the last prefetched quad
        const uint4 h0 = *(const uint4*)(supp + ((size_t)q0.x << 6) + (qi << 3));
        const uint4 h1 = *(const uint4*)(supp + ((size_t)q1.x << 6) + (qi << 3));
        const uint4 h2 = *(const uint4*)(supp + ((size_t)q2.x << 6) + (qi << 3));
        const uint4 h3 = *(const uint4*)(supp + ((size_t)q3.x << 6) + (qi << 3));
        const float v0 = __int_as_float(q0.y);
        const float v1 = __int_as_float(q1.y);
        const float v2 = __int_as_float(q2.y);
        const float v3 = __int_as_float(q3.y);
        float2 f;
        f = __half22float2(*(const __half2*)&h0.x); acc[0] += v0 * f.x; acc[1] += v0 * f.y;
        f = __half22float2(*(const __half2*)&h0.y); acc[2] += v0 * f.x; acc[3] += v0 * f.y;
        f = __half22float2(*(const __half2*)&h0.z); acc[4] += v0 * f.x; acc[5] += v0 * f.y;
        f = __half22float2(*(const __half2*)&h0.w); acc[6] += v0 * f.x; acc[7] += v0 * f.y;
        f = __half22float2(*(const __half2*)&h1.x); acc[0] += v1 * f.x; acc[1] += v1 * f.y;
        f = __half22float2(*(const __half2*)&h1.y); acc[2] += v1 * f.x; acc[3] += v1 * f.y;
        f = __half22float2(*(const __half2*)&h1.z); acc[4] += v1 * f.x; acc[5] += v1 * f.y;
        f = __half22float2(*(const __half2*)&h1.w); acc[6] += v1 * f.x; acc[7] += v1 * f.y;
        f = __half22float2(*(const __half2*)&h2.x); acc[0] += v2 * f.x; acc[1] += v2 * f.y;
        f = __half22float2(*(const __half2*)&h2.y); acc[2] += v2 * f.x; acc[3] += v2 * f.y;
        f = __half22float2(*(const __half2*)&h2.z); acc[4] += v2 * f.x; acc[5] += v2 * f.y;
        f = __half22float2(*(const __half2*)&h2.w); acc[6] += v2 * f.x; acc[7] += v2 * f.y;
        f = __half22float2(*(const __half2*)&h3.x); acc[0] += v3 * f.x; acc[1] += v3 * f.y;
        f = __half22float2(*(const __half2*)&h3.y); acc[2] += v3 * f.x; acc[3] += v3 * f.y;
        f = __half22float2(*(const __half2*)&h3.z); acc[4] += v3 * f.x; acc[5] += v3 * f.y;
        f = __half22float2(*(const __half2*)&h3.w); acc[6] += v3 * f.x; acc[7] += v3 * f.y;
        i += 4;
    }
    for (; i < e; i++) {
        const int2 p0 = g_epair[i];
        const float v0 = __int_as_float(p0.y);
        const uint4 h0 = *(const uint4*)(supp + ((size_t)p0.x << 6) + (qi << 3));
        float2 f;
        f = __half22float2(*(const __half2*)&h0.x); acc[0] += v0 * f.x; acc[1] += v0 * f.y;
        f = __half22float2(*(const __half2*)&h0.y); acc[2] += v0 * f.x; acc[3] += v0 * f.y;
        f = __half22float2(*(const __half2*)&h0.z); acc[4] += v0 * f.x; acc[5] += v0 * f.y;
        f = __half22float2(*(const __half2*)&h0.w); acc[6] += v0 * f.x; acc[7] += v0 * f.y;
    }

    const float4 b0 = *(const float4*)(bias + qi * 8);
    const float4 b1 = *(const float4*)(bias + qi * 8 + 4);
    float4 o0, o1;
    o0.x = fmaxf(acc[0] + b0.x, 0.f); o0.y = fmaxf(acc[1] + b0.y, 0.f);
    o0.z = fmaxf(acc[2] + b0.z, 0.f); o0.w = fmaxf(acc[3] + b0.w, 0.f);
    o1.x = fmaxf(acc[4] + b1.x, 0.f); o1.y = fmaxf(acc[5] + b1.y, 0.f);
    o1.z = fmaxf(acc[6] + b1.z, 0.f); o1.w = fmaxf(acc[7] + b1.w, 0.f);
    float* po = out + (size_t)r * FEAT + qi * 8;
    *(float4*)po       = o0;
    *(float4*)(po + 4) = o1;
}

// ---------------------------------------------------------------------------
extern "C" void kernel_launch(void* const* d_in, const int* in_sizes, int n_in,
                              void* d_out, int out_size) {
    const float* X    = (const float*)d_in[0];
    const int*   erow = (const int*)  d_in[1];
    const int*   ecol = (const int*)  d_in[2];
    const float* eval = (const float*)d_in[3];
    const float* W    = (const float*)d_in[4];
    const float* bias = (const float*)d_in[5];
    float* out = (float*)d_out;

    gemm_hist<<<N_NODES / 64, 256>>>(X, W, (const int4*)erow);
    scan_fused<<<64, 256>>>();
    reorder<<<N_EDGES / 2048, 256>>>((const int4*)erow, (const int4*)ecol,
                                     (const float4*)eval);
    spmm_fused<<<N_NODES / 32, 256>>>(out, bias);
}